// round 9
// baseline (speedup 1.0000x reference)
#include <cuda_runtime.h>
#include <math.h>

#define NN   512
#define DD   128
#define M_TOTAL 2048   // 4*512

// Scratch (device globals: no allocation allowed in kernel_launch)
__device__ float g_Pb[M_TOTAL * DD];  // x@W1 - x@W2 + bias
__device__ float g_Q [M_TOTAL * DD];  // x@W2

// ---------------- packed f32x2 helpers (Blackwell; NO packed max) ----------
typedef unsigned long long ull;

static __device__ __forceinline__ ull pk2(float a) {      // {a, a}
    ull r; unsigned ai = __float_as_uint(a);
    asm("mov.b64 %0, {%1, %1};" : "=l"(r) : "r"(ai));
    return r;
}
static __device__ __forceinline__ ull add2(ull a, ull b) {
    ull r; asm("add.rn.f32x2 %0, %1, %2;" : "=l"(r) : "l"(a), "l"(b));
    return r;
}
static __device__ __forceinline__ ull fma2(ull a, ull b, ull c) {
    ull r; asm("fma.rn.f32x2 %0, %1, %2, %3;" : "=l"(r) : "l"(a), "l"(b), "l"(c));
    return r;
}

union F4U2 { float4 f4; ull u[2]; };

static __device__ __forceinline__ float4 f4max(float4 a, float4 b) {
    float4 r;
    r.x = fmaxf(a.x, b.x); r.y = fmaxf(a.y, b.y);
    r.z = fmaxf(a.z, b.z); r.w = fmaxf(a.w, b.w);
    return r;
}

// ---------------- cp.async helpers ----------------
static __device__ __forceinline__ void cpasync16(unsigned dst, const void* src) {
    asm volatile("cp.async.cg.shared.global [%0], [%1], 16;"
                 :: "r"(dst), "l"(src));
}
#define CP_COMMIT() asm volatile("cp.async.commit_group;")
#define CP_WAIT(n)  asm volatile("cp.async.wait_group %0;" :: "n"(n))

// ---------------------------------------------------------------------------
// Kernel 1: fused dual GEMM, f32x2 FMAs.
//   A1 = x@W1 ; Q = x@W2 ; Pb = A1 - Q + bias (epilogue)
// grid 256 x 256 threads. Block = 8 rows; warp = 1 row; lane = 4 cols.
// W read once per block: 256 * 128KB = 33 MB L2 traffic.
// ---------------------------------------------------------------------------
__global__ __launch_bounds__(256)
void ec_gemm_kernel(const float* __restrict__ x,
                    const float* __restrict__ W,
                    const float* __restrict__ bias) {
    __shared__ float xs[8][DD];

    const int tid  = threadIdx.x;
    const int w    = tid >> 5;
    const int lane = tid & 31;
    const int rowBase = blockIdx.x * 8;

    ((float4*)xs)[tid] = __ldg(((const float4*)(x + (size_t)rowBase * DD)) + tid);
    __syncthreads();

    ull a1[2] = {0ull, 0ull};
    ull qq[2] = {0ull, 0ull};

    const float4* __restrict__ W4 = (const float4*)W;

    for (int kc = 0; kc < DD; kc += 4) {
        F4U2 w1v[4], w2v[4];
#pragma unroll
        for (int u = 0; u < 4; ++u) {
            w1v[u].f4 = __ldg(&W4[(kc + u) * 32 + lane]);
            w2v[u].f4 = __ldg(&W4[(kc + u + DD) * 32 + lane]);
        }
        const float4 xv = *(const float4*)&xs[w][kc];
        ull xp[4];
        xp[0] = pk2(xv.x); xp[1] = pk2(xv.y); xp[2] = pk2(xv.z); xp[3] = pk2(xv.w);
#pragma unroll
        for (int u = 0; u < 4; ++u) {
            a1[0] = fma2(xp[u], w1v[u].u[0], a1[0]);
            a1[1] = fma2(xp[u], w1v[u].u[1], a1[1]);
            qq[0] = fma2(xp[u], w2v[u].u[0], qq[0]);
            qq[1] = fma2(xp[u], w2v[u].u[1], qq[1]);
        }
    }

    F4U2 A, Q;
    A.u[0] = a1[0]; A.u[1] = a1[1];
    Q.u[0] = qq[0]; Q.u[1] = qq[1];

    const float4 b4 = __ldg(&((const float4*)bias)[lane]);
    float4 P;
    P.x = (A.f4.x - Q.f4.x) + b4.x;
    P.y = (A.f4.y - Q.f4.y) + b4.y;
    P.z = (A.f4.z - Q.f4.z) + b4.z;
    P.w = (A.f4.w - Q.f4.w) + b4.w;

    const int m = rowBase + w;
    ((float4*)g_Pb)[(size_t)m * 32 + lane] = P;
    ((float4*)g_Q )[(size_t)m * 32 + lane] = Q.f4;
}

// ---------------------------------------------------------------------------
// Kernel 2: dense masked max.
//   out[b,i,o] = max(0, Pb[b,i,o] + max_j (Q[b,j,o] + m[i,j]))
// grid 512 x 256 threads (8 warps); block = 4 i-rows -> 3.46 blocks/SM,
// single balanced wave. 48 KB dyn smem: qbuf[2][32*32] f4 (32 KB) +
// mpack[512][4] ull (16 KB). 16 chunks of 32 j, cp.async double-buffered.
// Warp w handles j = w*4..w*4+3 per chunk for all 4 rows (4x q reuse).
// Per j: 1 LDS.128 q + 2 bcast LDS.128 masks + 8 FADD2 + 16 FMNMX.
// ---------------------------------------------------------------------------
__global__ __launch_bounds__(256, 4)
void ec_maxred_kernel(const float* __restrict__ adj,
                      float* __restrict__ out) {
    extern __shared__ char dsm[];
    float4* qbuf = (float4*)dsm;                          // [2][1024]
    ull (*mpack)[4] = (ull (*)[4])(dsm + 32768);          // [512][4]

    const int tid  = threadIdx.x;
    const int w    = tid >> 5;
    const int lane = tid & 31;
    const int i0   = blockIdx.x * 4;     // first global row (b*NN + i)
    const int b    = i0 >> 9;

    const float4* __restrict__ Qb4 = ((const float4*)g_Q) + (size_t)b * NN * 32;

    // ---- stage chunk 0 (async) ----
    {
        unsigned dst0 = (unsigned)__cvta_generic_to_shared(qbuf);
#pragma unroll
        for (int t = 0; t < 4; ++t) {
            const int idx = tid + t * 256;
            cpasync16(dst0 + idx * 16, Qb4 + idx);
        }
        CP_COMMIT();
    }

    // ---- pre-pack ALL masks (4 rows x 512 j) while chunk 0 is in flight ----
    {
        const int pr = tid >> 6;          // row 0..3
        const int pj = (tid & 63) * 8;    // j base, 8 per thread
        const float4* arow4 =
            (const float4*)(adj + (size_t)(i0 + pr) * NN + pj);
        const float4 a0 = __ldg(arow4);
        const float4 a1 = __ldg(arow4 + 1);
        mpack[pj + 0][pr] = pk2(fmaf(a0.x, 1e38f, -1e38f));
        mpack[pj + 1][pr] = pk2(fmaf(a0.y, 1e38f, -1e38f));
        mpack[pj + 2][pr] = pk2(fmaf(a0.z, 1e38f, -1e38f));
        mpack[pj + 3][pr] = pk2(fmaf(a0.w, 1e38f, -1e38f));
        mpack[pj + 4][pr] = pk2(fmaf(a1.x, 1e38f, -1e38f));
        mpack[pj + 5][pr] = pk2(fmaf(a1.y, 1e38f, -1e38f));
        mpack[pj + 6][pr] = pk2(fmaf(a1.z, 1e38f, -1e38f));
        mpack[pj + 7][pr] = pk2(fmaf(a1.w, 1e38f, -1e38f));
    }

    float4 acc[4];
#pragma unroll
    for (int r = 0; r < 4; ++r)
        acc[r] = make_float4(-3.0e38f, -3.0e38f, -3.0e38f, -3.0e38f);

    for (int c = 0; c < 16; ++c) {
        if (c < 15) {     // stage next chunk into the other buffer
            unsigned dst = (unsigned)__cvta_generic_to_shared(
                               qbuf + ((c + 1) & 1) * 1024);
#pragma unroll
            for (int t = 0; t < 4; ++t) {
                const int idx = tid + t * 256;
                cpasync16(dst + idx * 16, Qb4 + (c + 1) * 1024 + idx);
            }
            CP_COMMIT();
            CP_WAIT(1);   // chunk c arrived
        } else {
            CP_WAIT(0);
        }
        __syncthreads();

        const float4* qc = qbuf + (c & 1) * 1024;
        const int jb = w * 4;
#pragma unroll
        for (int u = 0; u < 4; ++u) {
            const int jl = jb + u;
            const int jg = c * 32 + jl;
            F4U2 q;
            q.f4 = qc[jl * 32 + lane];

            const ulonglong2 m01 = *(const ulonglong2*)&mpack[jg][0];
            const ulonglong2 m23 = *(const ulonglong2*)&mpack[jg][2];

#define MROW2(ra, rb, mm2) {                                      \
            F4U2 ta, tb;                                          \
            ta.u[0] = add2(q.u[0], (mm2).x);                      \
            ta.u[1] = add2(q.u[1], (mm2).x);                      \
            tb.u[0] = add2(q.u[0], (mm2).y);                      \
            tb.u[1] = add2(q.u[1], (mm2).y);                      \
            acc[ra] = f4max(acc[ra], ta.f4);                      \
            acc[rb] = f4max(acc[rb], tb.f4); }

            MROW2(0, 1, m01)
            MROW2(2, 3, m23)
#undef MROW2
        }
        __syncthreads();   // before next stage overwrites buffer (c+1)&1
    }

    // ---- reduction: 8 warp-partials per row (reuse qbuf[0] = 16 KB) ----
    float4 (*buf)[4][32] = (float4 (*)[4][32])qbuf;

#pragma unroll
    for (int r = 0; r < 4; ++r) buf[w][r][lane] = acc[r];
    __syncthreads();

    if (w < 4) {           // warp w finalizes row i0 + w
        float4 v = buf[0][w][lane];
#pragma unroll
        for (int k = 1; k < 8; ++k) v = f4max(v, buf[k][w][lane]);

        const float4 p = __ldg(&((const float4*)g_Pb)[(size_t)(i0 + w) * 32 + lane]);
        float4 o;
        o.x = fmaxf(0.f, p.x + v.x);
        o.y = fmaxf(0.f, p.y + v.y);
        o.z = fmaxf(0.f, p.z + v.z);
        o.w = fmaxf(0.f, p.w + v.w);
        ((float4*)out)[(size_t)(i0 + w) * 32 + lane] = o;
    }
}

// ---------------------------------------------------------------------------
extern "C" void kernel_launch(void* const* d_in, const int* in_sizes, int n_in,
                              void* d_out, int out_size) {
    const float* x    = (const float*)d_in[0];   // (4,512,128)
    const float* adj  = (const float*)d_in[1];   // (4,512,512)
    const float* W    = (const float*)d_in[2];   // (256,128)
    const float* bias = (const float*)d_in[3];   // (128,)
    float*       out  = (float*)d_out;           // (4,512,128)

    const int DSM = 32768 + 16384;               // 48 KB dynamic smem
    cudaFuncSetAttribute(ec_maxred_kernel,
                         cudaFuncAttributeMaxDynamicSharedMemorySize, DSM);

    ec_gemm_kernel<<<M_TOTAL / 8, 256>>>(x, W, bias);
    ec_maxred_kernel<<<M_TOTAL / 4, 256, DSM>>>(adj, out);
}